// round 1
// baseline (speedup 1.0000x reference)
#include <cuda_runtime.h>
#include <math.h>

#define BATCH 16
#define NPTS 4096
#define TJ 256                       // targets per j-slice (shared tile)
#define JS (NPTS / TJ)               // 16 j-slices
#define RI 8                         // rows per thread
#define THREADS 256
#define ROWS_PER_BLOCK (THREADS * RI)       // 2048
#define ROW_TILES (NPTS / ROWS_PER_BLOCK)   // 2

// Per-direction row minimums of squared distance, stored as uint bit patterns.
// All stored values are >= 0, so IEEE float ordering == uint ordering and
// atomicMin on uint is an exact, deterministic float min.
__device__ unsigned int g_min[2][BATCH * NPTS];

__global__ void init_min_kernel() {
    int idx = blockIdx.x * blockDim.x + threadIdx.x;
    if (idx < 2 * BATCH * NPTS)
        (&g_min[0][0])[idx] = 0x7F800000u;  // +inf
}

// For each "src" point i (rows), compute min over a TJ-slice of "dst" points j
// of squared distance, using d2 = (s_i + s_j) - 2<p,t>, exactly the reference
// expansion. Combine slices across blocks with atomicMin.
__global__ __launch_bounds__(THREADS)
void chamfer_min_kernel(const float* __restrict__ src,
                        const float* __restrict__ dst,
                        int dir) {
    __shared__ float4 sh[TJ];

    const int slice   = blockIdx.x;
    const int rowTile = blockIdx.y;
    const int b       = blockIdx.z;

    // Load this block's dst slice into shared as (-2x, -2y, -2z, |t|^2)
    const float* dptr = dst + (size_t)b * NPTS * 3;
    for (int j = threadIdx.x; j < TJ; j += THREADS) {
        int jg = slice * TJ + j;
        float x = dptr[jg * 3 + 0];
        float y = dptr[jg * 3 + 1];
        float z = dptr[jg * 3 + 2];
        sh[j] = make_float4(-2.0f * x, -2.0f * y, -2.0f * z,
                            x * x + y * y + z * z);
    }
    __syncthreads();

    // Each thread owns RI rows (strided by THREADS for coalesced loads)
    const float* sptr = src + (size_t)b * NPTS * 3;
    const int i0 = rowTile * ROWS_PER_BLOCK + threadIdx.x;

    float px[RI], py[RI], pz[RI], si[RI], m[RI];
#pragma unroll
    for (int r = 0; r < RI; r++) {
        int i = i0 + r * THREADS;
        float x = sptr[i * 3 + 0];
        float y = sptr[i * 3 + 1];
        float z = sptr[i * 3 + 2];
        px[r] = x; py[r] = y; pz[r] = z;
        si[r] = x * x + y * y + z * z;
        m[r] = __int_as_float(0x7F800000);  // +inf
    }

    // Main loop: 1 LDS.128 + per pair (1 FADD + 3 FFMA + 1 FMNMX)
#pragma unroll 4
    for (int j = 0; j < TJ; j++) {
        float4 t = sh[j];
#pragma unroll
        for (int r = 0; r < RI; r++) {
            float d2 = fmaf(px[r], t.x,
                       fmaf(py[r], t.y,
                       fmaf(pz[r], t.z, si[r] + t.w)));
            m[r] = fminf(m[r], d2);
        }
    }

    unsigned int* gm = &g_min[dir][b * NPTS];
#pragma unroll
    for (int r = 0; r < RI; r++) {
        float v = fmaxf(m[r], 0.0f);  // clamp commutes with min
        atomicMin(&gm[i0 + r * THREADS], __float_as_uint(v));
    }
}

// Single-block deterministic reduction: mean of sqrt over both direction
// min arrays, scaled to match reference:
//   mean_b[ (mean_i sqrt(min1) + mean_j sqrt(min2)) / 2 ]
// = sum_all sqrt(min) / (2 * B * N)
__global__ void reduce_kernel(float* __restrict__ out) {
    __shared__ float ssum[1024];
    const unsigned int* gm = &g_min[0][0];
    float s = 0.0f;
    for (int idx = threadIdx.x; idx < 2 * BATCH * NPTS; idx += 1024)
        s += sqrtf(__uint_as_float(gm[idx]));
    ssum[threadIdx.x] = s;
    __syncthreads();
    for (int o = 512; o > 0; o >>= 1) {
        if (threadIdx.x < o) ssum[threadIdx.x] += ssum[threadIdx.x + o];
        __syncthreads();
    }
    if (threadIdx.x == 0)
        out[0] = ssum[0] / (2.0f * BATCH * NPTS);
}

extern "C" void kernel_launch(void* const* d_in, const int* in_sizes, int n_in,
                              void* d_out, int out_size) {
    const float* pred   = (const float*)d_in[0];
    const float* target = (const float*)d_in[1];
    float* out = (float*)d_out;

    init_min_kernel<<<(2 * BATCH * NPTS + 255) / 256, 256>>>();

    dim3 grid(JS, ROW_TILES, BATCH);
    chamfer_min_kernel<<<grid, THREADS>>>(pred, target, 0);  // pred -> target
    chamfer_min_kernel<<<grid, THREADS>>>(target, pred, 1);  // target -> pred

    reduce_kernel<<<1, 1024>>>(out);
}

// round 2
// speedup vs baseline: 1.4768x; 1.4768x over previous
#include <cuda_runtime.h>
#include <math.h>

#define BATCH 16
#define NPTS  4096
#define THREADS 128
#define RI 4                                  // rows per thread
#define ROWS_PER_BLOCK (THREADS * RI)         // 512
#define ROW_BLOCKS (NPTS / ROWS_PER_BLOCK)    // 8
#define TJ 1024                               // targets per shared slice
#define NSLICES (NPTS / TJ)                   // 4
#define NBLOCKS (ROW_BLOCKS * BATCH * 2)      // 256

__device__ float g_partial[NBLOCKS];

// Each block owns 512 complete rows of one (batch, direction) and loops over
// ALL 4096 targets in 4 shared slices. Row min is fully block-local -> sqrt
// and partial sum happen in-kernel (no atomics, no giant serial reduce).
//
// Inner math (per 2 pairs): 3x fma.rn.f32x2 (fma pipe) + 2x FMNMX (alu pipe).
// s_i is folded out of the loop: min_j(si+sj-2<p,t>) = si + min_j(sj-2<p,t>).
__global__ __launch_bounds__(THREADS)
void chamfer_kernel(const float* __restrict__ pred,
                    const float* __restrict__ target) {
    __shared__ float4 shA[TJ];   // (-2x, -2x, -2y, -2y)  duplicated for f32x2
    __shared__ float4 shB[TJ];   // (-2z, -2z,  sj,  sj)
    __shared__ float  ssum[THREADS];

    const int rowBlk = blockIdx.x;
    const int b      = blockIdx.y;
    const int dir    = blockIdx.z;

    const float* src = (dir == 0 ? pred : target) + (size_t)b * NPTS * 3;
    const float* dst = (dir == 0 ? target : pred) + (size_t)b * NPTS * 3;

    // Load this thread's RI rows (stride THREADS -> coalesced)
    const int i0 = rowBlk * ROWS_PER_BLOCK + threadIdx.x;
    float px[RI], py[RI], pz[RI], si[RI], m[RI];
#pragma unroll
    for (int r = 0; r < RI; r++) {
        int i = i0 + r * THREADS;
        float x = src[i * 3 + 0];
        float y = src[i * 3 + 1];
        float z = src[i * 3 + 2];
        px[r] = x; py[r] = y; pz[r] = z;
        si[r] = x * x + y * y + z * z;
        m[r] = __int_as_float(0x7F800000);   // +inf
    }

    // Pack row pairs (2rp, 2rp+1) into f32x2 operands
    unsigned long long pxx[RI / 2], pyy[RI / 2], pzz[RI / 2];
#pragma unroll
    for (int rp = 0; rp < RI / 2; rp++) {
        asm("mov.b64 %0, {%1, %2};" : "=l"(pxx[rp]) : "f"(px[2*rp]), "f"(px[2*rp+1]));
        asm("mov.b64 %0, {%1, %2};" : "=l"(pyy[rp]) : "f"(py[2*rp]), "f"(py[2*rp+1]));
        asm("mov.b64 %0, {%1, %2};" : "=l"(pzz[rp]) : "f"(pz[2*rp]), "f"(pz[2*rp+1]));
    }

    for (int s = 0; s < NSLICES; s++) {
        // Fill shared slice: target j as (-2x,-2y,-2z,|t|^2), each value doubled
        for (int j = threadIdx.x; j < TJ; j += THREADS) {
            int jg = s * TJ + j;
            float x = dst[jg * 3 + 0];
            float y = dst[jg * 3 + 1];
            float z = dst[jg * 3 + 2];
            float tx = -2.0f * x, ty = -2.0f * y, tz = -2.0f * z;
            float sj = x * x + y * y + z * z;
            shA[j] = make_float4(tx, tx, ty, ty);
            shB[j] = make_float4(tz, tz, sj, sj);
        }
        __syncthreads();

#pragma unroll 4
        for (int j = 0; j < TJ; j++) {
            // 2x LDS.128 (broadcast across warp)
            ulonglong2 a  = *reinterpret_cast<const ulonglong2*>(&shA[j]); // txx, tyy
            ulonglong2 bb = *reinterpret_cast<const ulonglong2*>(&shB[j]); // tzz, tww
#pragma unroll
            for (int rp = 0; rp < RI / 2; rp++) {
                unsigned long long d;
                asm("fma.rn.f32x2 %0, %1, %2, %3;"
                    : "=l"(d) : "l"(pxx[rp]), "l"(a.x), "l"(bb.y));
                asm("fma.rn.f32x2 %0, %1, %2, %0;"
                    : "+l"(d) : "l"(pyy[rp]), "l"(a.y));
                asm("fma.rn.f32x2 %0, %1, %2, %0;"
                    : "+l"(d) : "l"(pzz[rp]), "l"(bb.x));
                float lo, hi;
                asm("mov.b64 {%0, %1}, %2;" : "=f"(lo), "=f"(hi) : "l"(d));
                m[2*rp]   = fminf(m[2*rp],   lo);
                m[2*rp+1] = fminf(m[2*rp+1], hi);
            }
        }
        __syncthreads();
    }

    // Per-thread epilogue: add si back, clamp, sqrt, sum over owned rows
    float acc = 0.0f;
#pragma unroll
    for (int r = 0; r < RI; r++)
        acc += sqrtf(fmaxf(m[r] + si[r], 0.0f));

    // Deterministic block tree-reduce
    ssum[threadIdx.x] = acc;
    __syncthreads();
    for (int o = THREADS / 2; o > 0; o >>= 1) {
        if (threadIdx.x < o) ssum[threadIdx.x] += ssum[threadIdx.x + o];
        __syncthreads();
    }
    if (threadIdx.x == 0) {
        int bid = blockIdx.x + gridDim.x * (blockIdx.y + gridDim.y * blockIdx.z);
        g_partial[bid] = ssum[0];
    }
}

// Tiny deterministic final reduce over 256 fixed-slot partials.
__global__ void final_reduce_kernel(float* __restrict__ out) {
    __shared__ float ssum[NBLOCKS];
    ssum[threadIdx.x] = g_partial[threadIdx.x];
    __syncthreads();
    for (int o = NBLOCKS / 2; o > 0; o >>= 1) {
        if (threadIdx.x < o) ssum[threadIdx.x] += ssum[threadIdx.x + o];
        __syncthreads();
    }
    if (threadIdx.x == 0)
        out[0] = ssum[0] / (2.0f * BATCH * NPTS);
}

extern "C" void kernel_launch(void* const* d_in, const int* in_sizes, int n_in,
                              void* d_out, int out_size) {
    const float* pred   = (const float*)d_in[0];
    const float* target = (const float*)d_in[1];
    float* out = (float*)d_out;

    dim3 grid(ROW_BLOCKS, BATCH, 2);
    chamfer_kernel<<<grid, THREADS>>>(pred, target);
    final_reduce_kernel<<<1, NBLOCKS>>>(out);
}

// round 3
// speedup vs baseline: 1.6470x; 1.1152x over previous
#include <cuda_runtime.h>
#include <math.h>

#define BATCH 16
#define NPTS  4096
#define THREADS 128
#define NWARPS (THREADS / 32)                 // 4
#define RI 8                                  // rows per thread
#define ROWS_PER_BLOCK (THREADS * RI)         // 1024
#define ROW_TILES (NPTS / ROWS_PER_BLOCK)     // 4
#define TJ 256                                // cols per block (shared slice)
#define JSLICES (NPTS / TJ)                   // 16
#define NRED 128                              // partial-reduce blocks

// Global per-row / per-col minimum of squared distance, as uint bit patterns.
// Values are clamped >= 0 before punning, so uint order == float order and
// atomicMin is an exact, deterministic float min.
__device__ unsigned int g_min[2][BATCH * NPTS];   // [0]=row mins, [1]=col mins
__device__ float g_part[NRED];

__global__ void init_min_kernel() {
    int idx = blockIdx.x * blockDim.x + threadIdx.x;
    if (idx < 2 * BATCH * NPTS)
        (&g_min[0][0])[idx] = 0x7F800000u;    // +inf
}

// Single pass over the (pred x target) distance matrix: each d2 is computed
// ONCE and feeds both the row (pred->target) and col (target->pred) minimum.
// d2 = (si + sj) - 2<p,t>, identical to the reference expansion.
// Per 2 pairs: 1 add.f32x2 + 3 fma.f32x2 (fma pipe) + 2 FMNMX row (alu pipe);
// col reduction: per-thread tree + per-warp shfl-min, amortized.
__global__ __launch_bounds__(THREADS)
void chamfer_kernel(const float* __restrict__ pred,
                    const float* __restrict__ target) {
    __shared__ float4 shA[TJ];                // (-2x,-2x,-2y,-2y)
    __shared__ float4 shB[TJ];                // (-2z,-2z, sj, sj)
    __shared__ float  shColW[NWARPS][TJ];     // per-warp col mins

    const int jslice  = blockIdx.x;
    const int rowTile = blockIdx.y;
    const int b       = blockIdx.z;
    const int warp    = threadIdx.x >> 5;
    const int lane    = threadIdx.x & 31;

    const float* src = pred   + (size_t)b * NPTS * 3;
    const float* dst = target + (size_t)b * NPTS * 3;

    // Fill shared col slice
    for (int j = threadIdx.x; j < TJ; j += THREADS) {
        int jg = jslice * TJ + j;
        float x = dst[jg * 3 + 0];
        float y = dst[jg * 3 + 1];
        float z = dst[jg * 3 + 2];
        float tx = -2.0f * x, ty = -2.0f * y, tz = -2.0f * z;
        float sj = x * x + y * y + z * z;
        shA[j] = make_float4(tx, tx, ty, ty);
        shB[j] = make_float4(tz, tz, sj, sj);
    }

    // Load this thread's RI rows (stride THREADS -> coalesced)
    const int i0 = rowTile * ROWS_PER_BLOCK + threadIdx.x;
    float px[RI], py[RI], pz[RI], si[RI], rowm[RI];
#pragma unroll
    for (int r = 0; r < RI; r++) {
        int i = i0 + r * THREADS;
        float x = src[i * 3 + 0];
        float y = src[i * 3 + 1];
        float z = src[i * 3 + 2];
        px[r] = x; py[r] = y; pz[r] = z;
        si[r] = x * x + y * y + z * z;
        rowm[r] = __int_as_float(0x7F800000);
    }

    // Pack row pairs for f32x2
    unsigned long long pxx[RI/2], pyy[RI/2], pzz[RI/2], sii[RI/2];
#pragma unroll
    for (int rp = 0; rp < RI/2; rp++) {
        asm("mov.b64 %0, {%1, %2};" : "=l"(pxx[rp]) : "f"(px[2*rp]), "f"(px[2*rp+1]));
        asm("mov.b64 %0, {%1, %2};" : "=l"(pyy[rp]) : "f"(py[2*rp]), "f"(py[2*rp+1]));
        asm("mov.b64 %0, {%1, %2};" : "=l"(pzz[rp]) : "f"(pz[2*rp]), "f"(pz[2*rp+1]));
        asm("mov.b64 %0, {%1, %2};" : "=l"(sii[rp]) : "f"(si[2*rp]), "f"(si[2*rp+1]));
    }
    __syncthreads();

#pragma unroll 2
    for (int j = 0; j < TJ; j++) {
        ulonglong2 a  = *reinterpret_cast<const ulonglong2*>(&shA[j]); // txx,tyy
        ulonglong2 bb = *reinterpret_cast<const ulonglong2*>(&shB[j]); // tzz,sjj
        float cm[RI/2];
#pragma unroll
        for (int rp = 0; rp < RI/2; rp++) {
            float lo, hi;
            asm("{\n\t"
                ".reg .b64 t;\n\t"
                "add.rn.f32x2 t, %2, %3;\n\t"
                "fma.rn.f32x2 t, %4, %5, t;\n\t"
                "fma.rn.f32x2 t, %6, %7, t;\n\t"
                "fma.rn.f32x2 t, %8, %9, t;\n\t"
                "mov.b64 {%0, %1}, t;\n\t"
                "}"
                : "=f"(lo), "=f"(hi)
                : "l"(sii[rp]), "l"(bb.y),
                  "l"(pxx[rp]), "l"(a.x),
                  "l"(pyy[rp]), "l"(a.y),
                  "l"(pzz[rp]), "l"(bb.x));
            rowm[2*rp]   = fminf(rowm[2*rp],   lo);
            rowm[2*rp+1] = fminf(rowm[2*rp+1], hi);
            cm[rp] = fminf(lo, hi);
        }
        float c = fminf(fminf(cm[0], cm[1]), fminf(cm[2], cm[3]));
        // warp col-min
        c = fminf(c, __shfl_xor_sync(0xFFFFFFFFu, c, 16));
        c = fminf(c, __shfl_xor_sync(0xFFFFFFFFu, c, 8));
        c = fminf(c, __shfl_xor_sync(0xFFFFFFFFu, c, 4));
        c = fminf(c, __shfl_xor_sync(0xFFFFFFFFu, c, 2));
        c = fminf(c, __shfl_xor_sync(0xFFFFFFFFu, c, 1));
        if (lane == 0) shColW[warp][j] = c;   // single writer per (warp, j)
    }
    __syncthreads();

    // Row epilogue: clamp and combine across jslices
    unsigned int* grow = &g_min[0][b * NPTS];
#pragma unroll
    for (int r = 0; r < RI; r++) {
        float v = fmaxf(rowm[r], 0.0f);
        atomicMin(&grow[i0 + r * THREADS], __float_as_uint(v));
    }

    // Col epilogue: combine 4 warp slots, clamp, combine across rowTiles
    unsigned int* gcol = &g_min[1][b * NPTS];
    for (int j = threadIdx.x; j < TJ; j += THREADS) {
        float v = fminf(fminf(shColW[0][j], shColW[1][j]),
                        fminf(shColW[2][j], shColW[3][j]));
        v = fmaxf(v, 0.0f);
        atomicMin(&gcol[jslice * TJ + j], __float_as_uint(v));
    }
}

// Parallel sqrt+sum over both min arrays -> NRED partials (fixed slots).
__global__ void reduce_kernel() {
    __shared__ float ssum[256];
    const unsigned int* gm = &g_min[0][0];
    float s = 0.0f;
    for (int idx = blockIdx.x * 256 + threadIdx.x; idx < 2 * BATCH * NPTS;
         idx += NRED * 256)
        s += sqrtf(__uint_as_float(gm[idx]));
    ssum[threadIdx.x] = s;
    __syncthreads();
    for (int o = 128; o > 0; o >>= 1) {
        if (threadIdx.x < o) ssum[threadIdx.x] += ssum[threadIdx.x + o];
        __syncthreads();
    }
    if (threadIdx.x == 0) g_part[blockIdx.x] = ssum[0];
}

__global__ void final_kernel(float* __restrict__ out) {
    __shared__ float ssum[NRED];
    ssum[threadIdx.x] = g_part[threadIdx.x];
    __syncthreads();
    for (int o = NRED / 2; o > 0; o >>= 1) {
        if (threadIdx.x < o) ssum[threadIdx.x] += ssum[threadIdx.x + o];
        __syncthreads();
    }
    if (threadIdx.x == 0)
        out[0] = ssum[0] / (2.0f * BATCH * NPTS);
}

extern "C" void kernel_launch(void* const* d_in, const int* in_sizes, int n_in,
                              void* d_out, int out_size) {
    const float* pred   = (const float*)d_in[0];
    const float* target = (const float*)d_in[1];
    float* out = (float*)d_out;

    init_min_kernel<<<(2 * BATCH * NPTS + 255) / 256, 256>>>();

    dim3 grid(JSLICES, ROW_TILES, BATCH);   // 16 x 4 x 16 = 1024 blocks
    chamfer_kernel<<<grid, THREADS>>>(pred, target);

    reduce_kernel<<<NRED, 256>>>();
    final_kernel<<<1, NRED>>>(out);
}

// round 4
// speedup vs baseline: 1.7056x; 1.0355x over previous
#include <cuda_runtime.h>
#include <math.h>

#define BATCH 16
#define NPTS  4096
#define THREADS 256
#define RI 8                                   // rows per thread
#define ROWS_PER_BLOCK (THREADS * RI)          // 2048
#define ROW_TILES (NPTS / ROWS_PER_BLOCK)      // 2
#define TJ 256                                 // cols per shared slice
#define JSLICES (NPTS / TJ)                    // 16
#define NRED 128

// Per-direction row minimums of (sj - 2<p,t>) + si, clamped >= 0, stored as
// uint bit patterns (float order == uint order for non-negative floats), so
// atomicMin is an exact deterministic float min.
__device__ unsigned int g_min[2][BATCH * NPTS];
__device__ float g_part[NRED];

__global__ void init_min_kernel() {
    int idx = blockIdx.x * blockDim.x + threadIdx.x;
    if (idx < 2 * BATCH * NPTS)
        (&g_min[0][0])[idx] = 0x7F800000u;   // +inf
}

// Issue-bound core: per 2 pairs = 3 fma.rn.f32x2 (fma pipe) + 2 FMNMX (alu).
// si folded out of the inner loop; added back in the epilogue before clamp.
__global__ __launch_bounds__(THREADS)
void chamfer_min_kernel(const float* __restrict__ pred,
                        const float* __restrict__ target) {
    __shared__ float4 shA[TJ];   // (-2x, -2x, -2y, -2y)  duplicated for f32x2
    __shared__ float4 shB[TJ];   // (-2z, -2z,  sj,  sj)

    const int slice   = blockIdx.x;
    const int rowTile = blockIdx.y;
    const int bz      = blockIdx.z;           // 0..31
    const int b       = bz >> 1;
    const int dir     = bz & 1;

    const float* src = (dir == 0 ? pred : target) + (size_t)b * NPTS * 3;
    const float* dst = (dir == 0 ? target : pred) + (size_t)b * NPTS * 3;

    // Fill shared column slice
    for (int j = threadIdx.x; j < TJ; j += THREADS) {
        int jg = slice * TJ + j;
        float x = dst[jg * 3 + 0];
        float y = dst[jg * 3 + 1];
        float z = dst[jg * 3 + 2];
        float tx = -2.0f * x, ty = -2.0f * y, tz = -2.0f * z;
        float sj = x * x + y * y + z * z;
        shA[j] = make_float4(tx, tx, ty, ty);
        shB[j] = make_float4(tz, tz, sj, sj);
    }

    // Load RI rows, pack pairs for f32x2, keep si for the epilogue
    const int i0 = rowTile * ROWS_PER_BLOCK + threadIdx.x;
    float si[RI], rowm[RI];
    unsigned long long pxx[RI/2], pyy[RI/2], pzz[RI/2];
#pragma unroll
    for (int rp = 0; rp < RI/2; rp++) {
        int ia = i0 + (2*rp)     * THREADS;
        int ib = i0 + (2*rp + 1) * THREADS;
        float xa = src[ia*3+0], ya = src[ia*3+1], za = src[ia*3+2];
        float xb = src[ib*3+0], yb = src[ib*3+1], zb = src[ib*3+2];
        si[2*rp]   = xa*xa + ya*ya + za*za;
        si[2*rp+1] = xb*xb + yb*yb + zb*zb;
        asm("mov.b64 %0, {%1, %2};" : "=l"(pxx[rp]) : "f"(xa), "f"(xb));
        asm("mov.b64 %0, {%1, %2};" : "=l"(pyy[rp]) : "f"(ya), "f"(yb));
        asm("mov.b64 %0, {%1, %2};" : "=l"(pzz[rp]) : "f"(za), "f"(zb));
        rowm[2*rp]   = __int_as_float(0x7F800000);
        rowm[2*rp+1] = __int_as_float(0x7F800000);
    }
    __syncthreads();

#pragma unroll 4
    for (int j = 0; j < TJ; j++) {
        ulonglong2 a  = *reinterpret_cast<const ulonglong2*>(&shA[j]); // txx,tyy
        ulonglong2 bb = *reinterpret_cast<const ulonglong2*>(&shB[j]); // tzz,sjj
#pragma unroll
        for (int rp = 0; rp < RI/2; rp++) {
            float lo, hi;
            asm("{\n\t"
                ".reg .b64 t;\n\t"
                "fma.rn.f32x2 t, %2, %3, %4;\n\t"
                "fma.rn.f32x2 t, %5, %6, t;\n\t"
                "fma.rn.f32x2 t, %7, %8, t;\n\t"
                "mov.b64 {%0, %1}, t;\n\t"
                "}"
                : "=f"(lo), "=f"(hi)
                : "l"(pzz[rp]), "l"(bb.x), "l"(bb.y),
                  "l"(pyy[rp]), "l"(a.y),
                  "l"(pxx[rp]), "l"(a.x));
            rowm[2*rp]   = fminf(rowm[2*rp],   lo);
            rowm[2*rp+1] = fminf(rowm[2*rp+1], hi);
        }
    }

    // Epilogue: add si back, clamp, combine across slices
    unsigned int* gm = &g_min[dir][b * NPTS];
#pragma unroll
    for (int r = 0; r < RI; r++) {
        float v = fmaxf(rowm[r] + si[r], 0.0f);
        atomicMin(&gm[i0 + r * THREADS], __float_as_uint(v));
    }
}

// Parallel sqrt+sum -> NRED fixed-slot partials, then tiny final combine.
__global__ void reduce_kernel() {
    __shared__ float ssum[256];
    const unsigned int* gm = &g_min[0][0];
    float s = 0.0f;
    for (int idx = blockIdx.x * 256 + threadIdx.x; idx < 2 * BATCH * NPTS;
         idx += NRED * 256)
        s += sqrtf(__uint_as_float(gm[idx]));
    ssum[threadIdx.x] = s;
    __syncthreads();
    for (int o = 128; o > 0; o >>= 1) {
        if (threadIdx.x < o) ssum[threadIdx.x] += ssum[threadIdx.x + o];
        __syncthreads();
    }
    if (threadIdx.x == 0) g_part[blockIdx.x] = ssum[0];
}

__global__ void final_kernel(float* __restrict__ out) {
    __shared__ float ssum[NRED];
    ssum[threadIdx.x] = g_part[threadIdx.x];
    __syncthreads();
    for (int o = NRED / 2; o > 0; o >>= 1) {
        if (threadIdx.x < o) ssum[threadIdx.x] += ssum[threadIdx.x + o];
        __syncthreads();
    }
    if (threadIdx.x == 0)
        out[0] = ssum[0] / (2.0f * BATCH * NPTS);
}

extern "C" void kernel_launch(void* const* d_in, const int* in_sizes, int n_in,
                              void* d_out, int out_size) {
    const float* pred   = (const float*)d_in[0];
    const float* target = (const float*)d_in[1];
    float* out = (float*)d_out;

    init_min_kernel<<<(2 * BATCH * NPTS + 255) / 256, 256>>>();

    dim3 grid(JSLICES, ROW_TILES, BATCH * 2);   // 16 x 2 x 32 = 1024 blocks
    chamfer_min_kernel<<<grid, THREADS>>>(pred, target);

    reduce_kernel<<<NRED, 256>>>();
    final_kernel<<<1, NRED>>>(out);
}